// round 16
// baseline (speedup 1.0000x reference)
#include <cuda_runtime.h>
#include <cstdint>

#define RNODES 256
#define LUTWORDS 8192        // 2^18 bits / 32
#define MSAMP 512
#define SSTEPS 512
#define NIN 32               // D*B
#define NOUT 10
#define SPC 4                // samples per CTA
#define NCTA (MSAMP / SPC)   // 128 CTAs -> single wave, 1 CTA per SM

// Persistent scratch (device globals — no runtime allocation allowed)
__device__ unsigned g_lutpk[RNODES * LUTWORDS];   // 8 MB bit-packed LUT
__device__ unsigned g_xbits[MSAMP * SSTEPS];      // 1 MB: 32 input bits per (m,t)
__device__ unsigned g_Wlo[64 * RNODES];           // chunk-major low bytes of primes*W
__device__ unsigned g_hib[24 * RNODES];           // [b(0..2)][w(0..7)][j] hi bitplanes

// ---------------------------------------------------------------------------
// Per-warp bool-serialization detect: if x is int32-encoded, every byte at
// offset%4!=0 is zero. u8-encoded random bits false-negative prob ~2^-96.
// ---------------------------------------------------------------------------
__device__ __forceinline__ int detect_u8(const void* xraw) {
    const unsigned char* p = (const unsigned char*)xraw;
    unsigned lane = threadIdx.x & 31u;
    unsigned acc = 0;
    for (unsigned i = lane; i < 128; i += 32)
        if (i & 3) acc |= p[i];
    return __ballot_sync(0xffffffffu, acc != 0) != 0;
}

// ---------------------------------------------------------------------------
// Pack the 256MB int32 0/1 LUT into 8MB of bits. 8 elements/thread, 32768
// CTAs (262144 CTAs was CTA-launch-rate bound). DRAM-floor bound (~44us).
// ---------------------------------------------------------------------------
__global__ void k_lutpack(const int* __restrict__ lut) {
    unsigned T = blockIdx.x * 256u + threadIdx.x;          // 8,388,608 threads
    unsigned v[8];
#pragma unroll
    for (int i = 0; i < 8; i++)
        v[i] = (unsigned)lut[T + (unsigned)i * 8388608u];
    unsigned wbase = T >> 5;
#pragma unroll
    for (int i = 0; i < 8; i++) {
        unsigned m = __ballot_sync(0xffffffffu, v[i] & 1u);
        if ((threadIdx.x & 31u) == 0u)
            g_lutpk[wbase + (unsigned)i * 262144u] = m;
    }
}

// ---------------------------------------------------------------------------
// Fused prep: x bit-packing (grid-stride) + weight prep.
//   lo = Wp & 255  -> chunk-major u32 (4 bytes of k per word) for dp4a
//   hi = Wp >> 8 (0..6) -> 3 bitplanes over k, 8 words of 32 bits each
// ---------------------------------------------------------------------------
__global__ void k_prep(const void* __restrict__ xraw,
                       const void* __restrict__ wraw,
                       const int* __restrict__ primes) {
    const int flag = detect_u8(xraw);

    // ---- xpack: 8,388,608 bools -> 262,144 u32 words
    for (unsigned g = blockIdx.x * 256u + threadIdx.x;
         g < MSAMP * SSTEPS * 32u; g += 1024u * 256u) {
        unsigned v;
        if (flag) v = ((const unsigned char*)xraw)[g] & 1u;
        else      v = (unsigned)((const int*)xraw)[g] & 1u;
        unsigned m = __ballot_sync(0xffffffffu, v);
        if ((threadIdx.x & 31u) == 0u) g_xbits[g >> 5] = m;
    }

    // ---- wprep
    int t = blockIdx.x * 256 + threadIdx.x;
    if (t < RNODES * 8) {
        int j = t >> 3, w = t & 7;
        unsigned lo[8] = {0, 0, 0, 0, 0, 0, 0, 0};
        unsigned hb0 = 0, hb1 = 0, hb2 = 0;
        for (int kk = 0; kk < 32; kk++) {
            int k = w * 32 + kk;
            unsigned wv = flag ? (unsigned)(((const unsigned char*)wraw)[j * RNODES + k] & 1)
                               : ((unsigned)((const int*)wraw)[j * RNODES + k] & 1u);
            unsigned p = wv ? (unsigned)primes[k] : 0u;
            lo[kk >> 2] |= (p & 255u) << ((kk & 3) * 8);
            unsigned h = p >> 8;
            hb0 |= (h & 1u) << kk;
            hb1 |= ((h >> 1) & 1u) << kk;
            hb2 |= ((h >> 2) & 1u) << kk;
        }
        for (int cc = 0; cc < 8; cc++)
            g_Wlo[(w * 8 + cc) * RNODES + j] = lo[cc];
        g_hib[(0 * 8 + w) * RNODES + j] = hb0;
        g_hib[(1 * 8 + w) * RNODES + j] = hb1;
        g_hib[(2 * 8 + w) * RNODES + j] = hb2;
    }
}

// ---------------------------------------------------------------------------
// Main reservoir kernel: 4 samples per CTA, 128 CTAs, 256 threads, occ 1
// (the proven register operating point). Distance-3 software pipeline:
// samples rotate one per phase (4 phases per step, 1 barrier each); each
// sample's LUT gather stays in flight across the 3 other samples' phases
// (~650 cyc cover vs ~350 in the pair-pipelined version), and per-phase
// gather bursts halve (256 wavefronts), so L2 latency + wavefront drain
// fits inside the cover.
// ---------------------------------------------------------------------------
__global__ void __launch_bounds__(256, 1)
k_main(const void* __restrict__ xraw,
       const int* __restrict__ input_nodes,
       const void* __restrict__ initraw,
       const float* __restrict__ rW,
       const float* __restrict__ rb,
       float* __restrict__ out)
{
    __shared__ unsigned s_x[SPC][SSTEPS];                      // 8 KB
    __shared__ __align__(16) uint4 s_r4[SPC][16];              // 256B r-bytes per sample
    __shared__ __align__(16) unsigned s_rbits[SPC][8];         // r-bits per sample

    const int m0 = blockIdx.x * SPC;
    const int j = threadIdx.x;
    const int lane = j & 31, warp = j >> 5;

    // stage all samples' packed inputs
#pragma unroll
    for (int s = 0; s < SPC; s++)
        for (int i = j; i < SSTEPS; i += 256)
            s_x[s][i] = g_xbits[(m0 + s) * SSTEPS + i];

    // weights into registers (static across all 512 steps)
    unsigned Wlo[64];
#pragma unroll
    for (int c = 0; c < 64; c++) Wlo[c] = g_Wlo[c * RNODES + j];
    unsigned HB0[8], HB1[8], HB2[8];
#pragma unroll
    for (int w = 0; w < 8; w++) {
        HB0[w] = g_hib[(0 * 8 + w) * RNODES + j];
        HB1[w] = g_hib[(1 * 8 + w) * RNODES + j];
        HB2[w] = g_hib[(2 * 8 + w) * RNODES + j];
    }

    int isin = 0, ipos = 0;
    for (int i = 0; i < NIN; i++) {
        int n = input_nodes[i];
        if (n == j) { isin = 1; ipos = i; }
    }

    const int flag = detect_u8(xraw);
    unsigned rinit = flag ? (unsigned)(((const unsigned char*)initraw)[j] & 1)
                          : ((unsigned)((const int*)initraw)[j] & 1u);

    const unsigned* lutp = g_lutpk + ((unsigned)j << 13);

    // dot for one sample from published shared state
    auto dot = [&](int s) -> unsigned {
        const uint4* q = s_r4[s];
        unsigned a0 = 0, a1 = 0, a2 = 0, a3 = 0;
#pragma unroll
        for (int c = 0; c < 16; c++) {
            uint4 v = q[c];
            a0 = __dp4a(v.x, Wlo[4 * c + 0], a0);
            a1 = __dp4a(v.y, Wlo[4 * c + 1], a1);
            a2 = __dp4a(v.z, Wlo[4 * c + 2], a2);
            a3 = __dp4a(v.w, Wlo[4 * c + 3], a3);
        }
        uint4 hA = *(const uint4*)&s_rbits[s][0];
        uint4 hB = *(const uint4*)&s_rbits[s][4];
        unsigned rw0 = hA.x, rw1 = hA.y, rw2 = hA.z, rw3 = hA.w;
        unsigned rw4 = hB.x, rw5 = hB.y, rw6 = hB.z, rw7 = hB.w;
        unsigned h0 = __popc(rw0 & HB0[0]) + __popc(rw1 & HB0[1]) +
                      __popc(rw2 & HB0[2]) + __popc(rw3 & HB0[3]) +
                      __popc(rw4 & HB0[4]) + __popc(rw5 & HB0[5]) +
                      __popc(rw6 & HB0[6]) + __popc(rw7 & HB0[7]);
        unsigned h1 = __popc(rw0 & HB1[0]) + __popc(rw1 & HB1[1]) +
                      __popc(rw2 & HB1[2]) + __popc(rw3 & HB1[3]) +
                      __popc(rw4 & HB1[4]) + __popc(rw5 & HB1[5]) +
                      __popc(rw6 & HB1[6]) + __popc(rw7 & HB1[7]);
        unsigned h2 = __popc(rw0 & HB2[0]) + __popc(rw1 & HB2[1]) +
                      __popc(rw2 & HB2[2]) + __popc(rw3 & HB2[3]) +
                      __popc(rw4 & HB2[4]) + __popc(rw5 & HB2[5]) +
                      __popc(rw6 & HB2[6]) + __popc(rw7 & HB2[7]);
        return (a0 + a1) + (a2 + a3) + ((h0 + 2u * h1 + 4u * h2) << 8);
    };
    auto publish = [&](int s, unsigned r) {
        unsigned b = __ballot_sync(0xffffffffu, r);
        ((unsigned char*)s_r4[s])[j] = (unsigned char)r;
        if (lane == 0) s_rbits[s][warp] = b;
    };

    __syncthreads();   // s_x visible

    // ---- prologue: publish state 0 for all samples (x[0] overwrite applied)
#pragma unroll
    for (int s = 0; s < SPC; s++) {
        unsigned r = isin ? ((s_x[s][0] >> ipos) & 1u) : rinit;
        publish(s, r);
    }
    __syncthreads();

    // prime the rotation: idx+gather for step 0 of every sample
    unsigned idx[SPC], wv[SPC];
#pragma unroll
    for (int s = 0; s < SPC; s++) {
        idx[s] = dot(s);
        wv[s] = __ldg(lutp + (idx[s] >> 5));
    }
    __syncthreads();   // prologue reads of s_r4 done before loop rewrites them

    for (int t = 0; t < SSTEPS; t++) {
#pragma unroll
        for (int s = 0; s < SPC; s++) {
            // consume sample s's load for step t (issued 4 phases ago)
            unsigned r = (wv[s] >> (idx[s] & 31u)) & 1u;
            if (isin && t + 1 < SSTEPS)
                r = (s_x[s][t + 1] >> ipos) & 1u;
            publish(s, r);
            __syncthreads();
            // issue sample s's dot+gather for step t+1 (drains over the
            // next 3 phases; dead work on the final iteration, harmless)
            idx[s] = dot(s);
            wv[s] = __ldg(lutp + (idx[s] >> 5));
        }
    }
    __syncthreads();

    // final states of all 4 samples are published in s_r4 (bytes)
    // readout: out[m, o] = sum_j rW[o, j] * rf[j] + rb[o]
    if (j < SPC * 16) {                        // 64 threads: sample = j/16, out = j%16
        int s = j >> 4, o = j & 15;
        if (o < NOUT) {
            const unsigned char* rf = (const unsigned char*)s_r4[s];
            float acc = rb[o];
            const float* wr = rW + o * RNODES;
            for (int k = 0; k < RNODES; k++)
                acc += wr[k] * (float)rf[k];
            out[(m0 + s) * NOUT + o] = acc;
        }
    }
}

// ---------------------------------------------------------------------------
// d_in order: x, input_nodes, lut, W_res, primes, init_res, readout_W, readout_b
// ---------------------------------------------------------------------------
extern "C" void kernel_launch(void* const* d_in, const int* in_sizes, int n_in,
                              void* d_out, int out_size) {
    (void)in_sizes; (void)n_in; (void)out_size;
    const void*  x       = d_in[0];
    const int*   innodes = (const int*)d_in[1];
    const int*   lut     = (const int*)d_in[2];
    const void*  wres    = d_in[3];
    const int*   primes  = (const int*)d_in[4];
    const void*  initres = d_in[5];
    const float* rW      = (const float*)d_in[6];
    const float* rb      = (const float*)d_in[7];
    float* out = (float*)d_out;

    k_lutpack<<<32768, 256>>>(lut);
    k_prep<<<1024, 256>>>(x, wres, primes);
    k_main<<<NCTA, 256>>>(x, innodes, initres, rW, rb, out);
}